// round 5
// baseline (speedup 1.0000x reference)
#include <cuda_runtime.h>
#include <cuda_fp16.h>
#include <float.h>

#define NROWS 8192
#define DIM   2048

typedef unsigned short u16;
typedef unsigned int   u32;
typedef unsigned long long u64;

// ---------------- scratch (device globals; no allocation allowed) ----------------
__device__ u16 g_Xh[2][(size_t)NROWS*DIM], g_Xl[2][(size_t)NROWS*DIM];
__device__ u16 g_Wh[8][(size_t)DIM*DIM],   g_Wl[8][(size_t)DIM*DIM];
__device__ u16 g_Kth[2][(size_t)NROWS*DIM], g_Ktl[2][(size_t)NROWS*DIM];
__device__ u16 g_Qth[2][(size_t)NROWS*DIM], g_Qtl[2][(size_t)NROWS*DIM];
__device__ u16 g_Vh[2][(size_t)NROWS*DIM],  g_Vl[2][(size_t)NROWS*DIM];
__device__ u16 g_wh[2][(size_t)DIM*DIM],    g_wl[2][(size_t)DIM*DIM];
__device__ u16 g_Oh[2][(size_t)NROWS*DIM],  g_Ol[2][(size_t)NROWS*DIM];

// ---------------- helpers ----------------
__device__ __forceinline__ u32 smem_u32(const void* p) {
    u32 a;
    asm("{ .reg .u64 t; cvta.to.shared.u64 t, %1; cvt.u32.u64 %0, t; }" : "=r"(a) : "l"(p));
    return a;
}

constexpr float INV2048 = 1.0f / 2048.0f;

// split fp32 -> fp16 hi + fp16 lo*2048 (scaled so correction products stay normal-range)
__device__ __forceinline__ void split1h(float v, u16& h, u16& l) {
    __half hh = __float2half_rn(v);
    float r = (v - __half2float(hh)) * 2048.0f;
    __half ll = __float2half_rn(r);
    h = __half_as_ushort(hh);
    l = __half_as_ushort(ll);
}

__device__ __forceinline__ float2 corr2f(u32 c) {
    __half2 h = *(__half2*)&c;
    return __half22float2(h);
}

#define CP_ASYNC16(dst, src) \
    asm volatile("cp.async.cg.shared.global [%0], [%1], 16;" :: "r"(dst), "l"(src))
#define CP_COMMIT()  asm volatile("cp.async.commit_group;" ::: "memory")
#define CP_WAIT0()   asm volatile("cp.async.wait_group 0;" ::: "memory")
#define CP_WAIT1()   asm volatile("cp.async.wait_group 1;" ::: "memory")

#define LDSM_X4(r, addr) \
    asm volatile("ldmatrix.sync.aligned.m8n8.x4.shared.b16 {%0,%1,%2,%3}, [%4];" \
        : "=r"((r)[0]), "=r"((r)[1]), "=r"((r)[2]), "=r"((r)[3]) : "r"(addr))

#define MMA16816F(d, a, b) \
    asm volatile("mma.sync.aligned.m16n8k16.row.col.f32.f16.f16.f32 " \
        "{%0,%1,%2,%3}, {%4,%5,%6,%7}, {%8,%9}, {%0,%1,%2,%3};" \
        : "+f"((d)[0]), "+f"((d)[1]), "+f"((d)[2]), "+f"((d)[3]) \
        : "r"((a)[0]), "r"((a)[1]), "r"((a)[2]), "r"((a)[3]), "r"((b)[0]), "r"((b)[1]))

#define MMA16816H(d, a, b) \
    asm volatile("mma.sync.aligned.m16n8k16.row.col.f16.f16.f16.f16 " \
        "{%0,%1}, {%2,%3,%4,%5}, {%6,%7}, {%0,%1};" \
        : "+r"((d)[0]), "+r"((d)[1]) \
        : "r"((a)[0]), "r"((a)[1]), "r"((a)[2]), "r"((a)[3]), "r"((b)[0]), "r"((b)[1]))

// ---------------- batched GEMM jobs ----------------
struct Job {
    const u16 *Ah, *Al, *Bh, *Bl;
    const float *bias, *res;
    float *C;
    u16 *Eh, *El;
};
struct Jobs { Job j[4]; };

// ---------------- GEMM: C[M,N] = A * B^T via fp16x3 split ----------------
// main pass f32 accum; two correction passes share one f16 accumulator (x2048 scaled lo)
// EMODE: 0 = fp32 C out, 1 = emit split planes [M][N], 2 = emit transposed planes [N][M]
constexpr int PLANE_BYTES = 128 * 128;          // 16KB: 128 rows x 64 fp16
constexpr int STAGE_BYTES = 4 * PLANE_BYTES;
constexpr int NSTAGE = 3;
constexpr int SMEM_TOTAL = NSTAGE * STAGE_BYTES;  // 196608

template <int EMODE, bool BIAS, bool RES>
__global__ void __launch_bounds__(256, 1) gemm_fp16x3(Jobs jobs, int M, int N, int K) {
    extern __shared__ char smem[];
    const Job j = jobs.j[blockIdx.z];
    const int tid = threadIdx.x;
    const int lane = tid & 31;
    const int wid = tid >> 5;
    const int warpM = wid & 1;
    const int warpN = wid >> 1;
    const int m0 = blockIdx.y * 128;
    const int n0 = blockIdx.x * 128;
    const u32 sb = smem_u32(smem);

    float acc[4][4][4];
    u32 corr[4][4][2];
#pragma unroll
    for (int a = 0; a < 4; a++)
#pragma unroll
        for (int b = 0; b < 4; b++) {
#pragma unroll
            for (int c = 0; c < 4; c++) acc[a][b][c] = 0.f;
            corr[a][b][0] = 0u; corr[a][b][1] = 0u;
        }

    const u16* planes[4] = {j.Ah, j.Al, j.Bh, j.Bl};

    auto issue = [&](int t) {
        const int k0 = t * 64;
        const u32 stg = sb + (t % NSTAGE) * STAGE_BYTES;
#pragma unroll
        for (int p = 0; p < 4; p++) {
            const u16* src = planes[p];
            const int r0 = (p < 2) ? m0 : n0;
            const u32 pb = stg + p * PLANE_BYTES;
#pragma unroll
            for (int it = 0; it < 4; it++) {
                int idx = tid + it * 256;
                int r = idx >> 3, c = idx & 7;
                const u16* g = src + (size_t)(r0 + r) * K + k0 + c * 8;
                u32 d = pb + r * 128 + ((c ^ (r & 7)) << 4);
                CP_ASYNC16(d, g);
            }
        }
    };

    issue(0); CP_COMMIT();
    issue(1); CP_COMMIT();

    const int T = K / 64;
    for (int t = 0; t < T; t++) {
        if (t + 2 < T) { CP_WAIT1(); } else { CP_WAIT0(); }
        __syncthreads();

        const u32 stg = sb + (t % NSTAGE) * STAGE_BYTES;
        const u32 aH = stg, aL = stg + PLANE_BYTES;
        const u32 bH = stg + 2 * PLANE_BYTES, bL = stg + 3 * PLANE_BYTES;

#pragma unroll
        for (int step = 0; step < 4; step++) {
            u32 ra[4][4], la[4][4];
#pragma unroll
            for (int mf = 0; mf < 4; mf++) {
                int row = warpM * 64 + mf * 16 + (lane & 15);
                int chunk = step * 2 + (lane >> 4);
                u32 off = row * 128 + ((chunk ^ (row & 7)) << 4);
                LDSM_X4(ra[mf], aH + off);
                LDSM_X4(la[mf], aL + off);
            }
            u32 rb[2][4], lb[2][4];
#pragma unroll
            for (int np = 0; np < 2; np++) {
                int jj = lane >> 3;
                int row = warpN * 32 + np * 16 + ((jj >> 1) << 3) + (lane & 7);
                int chunk = step * 2 + (jj & 1);
                u32 off = row * 128 + ((chunk ^ (row & 7)) << 4);
                LDSM_X4(rb[np], bH + off);
                LDSM_X4(lb[np], bL + off);
            }
            // main: f32 accum
#pragma unroll
            for (int mf = 0; mf < 4; mf++)
#pragma unroll
                for (int nf = 0; nf < 4; nf++)
                    MMA16816F(acc[mf][nf], ra[mf], &rb[nf >> 1][(nf & 1) * 2]);
            // corrections: shared f16 accum (values ~2048x true scale)
#pragma unroll
            for (int mf = 0; mf < 4; mf++)
#pragma unroll
                for (int nf = 0; nf < 4; nf++)
                    MMA16816H(corr[mf][nf], ra[mf], &lb[nf >> 1][(nf & 1) * 2]);
#pragma unroll
            for (int mf = 0; mf < 4; mf++)
#pragma unroll
                for (int nf = 0; nf < 4; nf++)
                    MMA16816H(corr[mf][nf], la[mf], &rb[nf >> 1][(nf & 1) * 2]);
        }

        if (t + 2 < T) { issue(t + 2); CP_COMMIT(); }
    }

    if (EMODE == 2) {
        // transposed emission: stage fp32 through smem, then coalesced plane stores
        __syncthreads();
        float* stg = (float*)smem;
#pragma unroll
        for (int mf = 0; mf < 4; mf++) {
#pragma unroll
            for (int nf = 0; nf < 4; nf++) {
                float2 c0 = corr2f(corr[mf][nf][0]);
                float2 c1 = corr2f(corr[mf][nf][1]);
                const float* a = acc[mf][nf];
                int cl = warpN * 32 + nf * 8 + (lane & 3) * 2;
                int rl0 = warpM * 64 + mf * 16 + (lane >> 2);
                stg[cl * 132 + rl0]       = a[0] + c0.x * INV2048;
                stg[(cl + 1) * 132 + rl0] = a[1] + c0.y * INV2048;
                stg[cl * 132 + rl0 + 8]       = a[2] + c1.x * INV2048;
                stg[(cl + 1) * 132 + rl0 + 8] = a[3] + c1.y * INV2048;
            }
        }
        __syncthreads();
#pragma unroll 4
        for (int i = 0; i < 64; i++) {
            int idx = tid + i * 256;
            int c = idx >> 7, r = idx & 127;
            float v = stg[c * 132 + r];
            if (BIAS) v += j.bias[n0 + c];
            u16 h, l;
            split1h(v, h, l);
            size_t o = (size_t)(n0 + c) * M + m0 + r;
            j.Eh[o] = h;
            j.El[o] = l;
        }
        return;
    }

    // direct register epilogue (EMODE 0/1)
#pragma unroll
    for (int mf = 0; mf < 4; mf++) {
        const int rbase = m0 + warpM * 64 + mf * 16 + (lane >> 2);
#pragma unroll
        for (int nf = 0; nf < 4; nf++) {
            const int c = n0 + warpN * 32 + nf * 8 + (lane & 3) * 2;
            const float* a = acc[mf][nf];
            float2 cr[2] = {corr2f(corr[mf][nf][0]), corr2f(corr[mf][nf][1])};
#pragma unroll
            for (int h = 0; h < 2; h++) {
                const int r = rbase + h * 8;
                float vx = a[h * 2 + 0] + cr[h].x * INV2048;
                float vy = a[h * 2 + 1] + cr[h].y * INV2048;
                if (BIAS) {
                    float2 b2 = *(const float2*)&j.bias[c];
                    vx += b2.x; vy += b2.y;
                }
                if (RES) {
                    float2 r2 = *(const float2*)&j.res[(size_t)r * N + c];
                    vx += r2.x; vy += r2.y;
                }
                if (EMODE == 1) {
                    u16 hx, lx, hy, ly;
                    split1h(vx, hx, lx);
                    split1h(vy, hy, ly);
                    *(ushort2*)&j.Eh[(size_t)r * N + c] = make_ushort2(hx, hy);
                    *(ushort2*)&j.El[(size_t)r * N + c] = make_ushort2(lx, ly);
                } else {
                    *(float2*)&j.C[(size_t)r * N + c] = make_float2(vx, vy);
                }
            }
        }
    }
}

// ---------------- conversion kernels ----------------
__global__ void __launch_bounds__(256) convert_in(const float* __restrict__ x,
                                                  const float* __restrict__ y,
                                                  u16* __restrict__ xh, u16* __restrict__ xl,
                                                  u16* __restrict__ yh, u16* __restrict__ yl) {
    const float* in = blockIdx.y ? y : x;
    u16* hi = blockIdx.y ? yh : xh;
    u16* lo = blockIdx.y ? yl : xl;
    size_t i = (size_t)blockIdx.x * 256 + threadIdx.x;
    float4 v = ((const float4*)in)[i];
    ushort4 h, l;
    split1h(v.x, h.x, l.x); split1h(v.y, h.y, l.y);
    split1h(v.z, h.z, l.z); split1h(v.w, h.w, l.w);
    ((ushort4*)hi)[i] = h;
    ((ushort4*)lo)[i] = l;
}

struct WJobs {
    const float* src[8];
    u16* h[8];
    u16* l[8];
};

// each W [in][out] fp32 -> planes [out][in] fp16 hi/lo (scaled lo)
__global__ void __launch_bounds__(256) convert_w(WJobs w) {
    __shared__ float t[32][33];
    const float* in = w.src[blockIdx.z];
    u16* hi = w.h[blockIdx.z];
    u16* lo = w.l[blockIdx.z];
    const int c0 = blockIdx.x * 32, r0 = blockIdx.y * 32;
    const int tx = threadIdx.x & 31, ty = threadIdx.x >> 5;
#pragma unroll
    for (int jj = 0; jj < 32; jj += 8)
        t[ty + jj][tx] = in[(size_t)(r0 + ty + jj) * DIM + c0 + tx];
    __syncthreads();
#pragma unroll
    for (int jj = 0; jj < 32; jj += 8) {
        float v = t[tx][ty + jj];
        u16 h, l;
        split1h(v, h, l);
        size_t o = (size_t)(c0 + ty + jj) * DIM + r0 + tx;
        hi[o] = h;
        lo[o] = l;
    }
}

// ---------------- softmax (in-place on d_out att region + emit fp16 planes) ----------------
__global__ void __launch_bounds__(256) softmax_kernel(float* att0, float* att1,
                                                      u16* wh0, u16* wl0,
                                                      u16* wh1, u16* wl1) {
    float* att = blockIdx.y ? att1 : att0;
    u16* wh = blockIdx.y ? wh1 : wh0;
    u16* wl = blockIdx.y ? wl1 : wl0;
    const int row = blockIdx.x;
    const int tid = threadIdx.x;
    float* r = att + (size_t)row * DIM;
    __shared__ float red[8];

    float v[8];
    float mx = -FLT_MAX;
#pragma unroll
    for (int i = 0; i < 8; i++) {
        v[i] = r[tid + i * 256];
        mx = fmaxf(mx, v[i]);
    }
#pragma unroll
    for (int o = 16; o > 0; o >>= 1) mx = fmaxf(mx, __shfl_xor_sync(0xffffffffu, mx, o));
    if ((tid & 31) == 0) red[tid >> 5] = mx;
    __syncthreads();
    mx = red[0];
#pragma unroll
    for (int w = 1; w < 8; w++) mx = fmaxf(mx, red[w]);
    __syncthreads();

    float s = 0.f;
#pragma unroll
    for (int i = 0; i < 8; i++) {
        v[i] = __expf(v[i] - mx);
        s += v[i];
    }
#pragma unroll
    for (int o = 16; o > 0; o >>= 1) s += __shfl_xor_sync(0xffffffffu, s, o);
    if ((tid & 31) == 0) red[tid >> 5] = s;
    __syncthreads();
    s = red[0];
#pragma unroll
    for (int w = 1; w < 8; w++) s += red[w];
    const float inv = 1.f / s;

#pragma unroll
    for (int i = 0; i < 8; i++) {
        float w = v[i] * inv;
        int col = tid + i * 256;
        r[col] = w;
        u16 h, l;
        split1h(w, h, l);
        wh[(size_t)row * DIM + col] = h;
        wl[(size_t)row * DIM + col] = l;
    }
}

// ---------------- host driver ----------------
extern "C" void kernel_launch(void* const* d_in, const int* in_sizes, int n_in,
                              void* d_out, int out_size) {
    cudaFuncSetAttribute(gemm_fp16x3<2, true, false>, cudaFuncAttributeMaxDynamicSharedMemorySize, SMEM_TOTAL);
    cudaFuncSetAttribute(gemm_fp16x3<1, true, false>, cudaFuncAttributeMaxDynamicSharedMemorySize, SMEM_TOTAL);
    cudaFuncSetAttribute(gemm_fp16x3<0, false, false>, cudaFuncAttributeMaxDynamicSharedMemorySize, SMEM_TOTAL);
    cudaFuncSetAttribute(gemm_fp16x3<1, false, false>, cudaFuncAttributeMaxDynamicSharedMemorySize, SMEM_TOTAL);
    cudaFuncSetAttribute(gemm_fp16x3<0, true, true>, cudaFuncAttributeMaxDynamicSharedMemorySize, SMEM_TOTAL);

    const float* x = (const float*)d_in[0];
    const float* y = (const float*)d_in[1];
    // weight/bias order: QK, QQ, QV, QO, FK, FQ, FV, FO at d_in[2..17] (w,b pairs)
    const float* W[8];
    const float* B[8];
    for (int i = 0; i < 8; i++) {
        W[i] = (const float*)d_in[2 + 2 * i];
        B[i] = (const float*)d_in[3 + 2 * i];
    }

    u16 *Xh[2], *Xl[2], *Wh[8], *Wl[8], *Kth[2], *Ktl[2], *Qth[2], *Qtl[2];
    u16 *Vh[2], *Vl[2], *wh[2], *wl[2], *Oh[2], *Ol[2];
    u16 *base;
    cudaGetSymbolAddress((void**)&base, g_Xh);
    for (int b = 0; b < 2; b++) { Xh[b] = base + (size_t)b * NROWS * DIM; }
    cudaGetSymbolAddress((void**)&base, g_Xl);
    for (int b = 0; b < 2; b++) { Xl[b] = base + (size_t)b * NROWS * DIM; }
    cudaGetSymbolAddress((void**)&base, g_Wh);
    for (int i = 0; i < 8; i++) { Wh[i] = base + (size_t)i * DIM * DIM; }
    cudaGetSymbolAddress((void**)&base, g_Wl);
    for (int i = 0; i < 8; i++) { Wl[i] = base + (size_t)i * DIM * DIM; }
    cudaGetSymbolAddress((void**)&base, g_Kth);
    for (int b = 0; b < 2; b++) { Kth[b] = base + (size_t)b * NROWS * DIM; }
    cudaGetSymbolAddress((void**)&base, g_Ktl);
    for (int b = 0; b < 2; b++) { Ktl[b] = base + (size_t)b * NROWS * DIM; }
    cudaGetSymbolAddress((void**)&base, g_Qth);
    for (int b = 0; b < 2; b++) { Qth[b] = base + (size_t)b * NROWS * DIM; }
    cudaGetSymbolAddress((void**)&base, g_Qtl);
    for (int b = 0; b < 2; b++) { Qtl[b] = base + (size_t)b * NROWS * DIM; }
    cudaGetSymbolAddress((void**)&base, g_Vh);
    for (int b = 0; b < 2; b++) { Vh[b] = base + (size_t)b * NROWS * DIM; }
    cudaGetSymbolAddress((void**)&base, g_Vl);
    for (int b = 0; b < 2; b++) { Vl[b] = base + (size_t)b * NROWS * DIM; }
    cudaGetSymbolAddress((void**)&base, g_wh);
    for (int b = 0; b < 2; b++) { wh[b] = base + (size_t)b * DIM * DIM; }
    cudaGetSymbolAddress((void**)&base, g_wl);
    for (int b = 0; b < 2; b++) { wl[b] = base + (size_t)b * DIM * DIM; }
    cudaGetSymbolAddress((void**)&base, g_Oh);
    for (int b = 0; b < 2; b++) { Oh[b] = base + (size_t)b * NROWS * DIM; }
    cudaGetSymbolAddress((void**)&base, g_Ol);
    for (int b = 0; b < 2; b++) { Ol[b] = base + (size_t)b * NROWS * DIM; }

    float* out = (float*)d_out;
    float* outQy   = out;
    float* outQatt = outQy + (size_t)NROWS * DIM;
    float* outFy   = outQatt + (size_t)DIM * DIM;
    float* outFatt = outFy + (size_t)NROWS * DIM;
    float* att[2] = {outQatt, outFatt};
    float* outY[2] = {outQy, outFy};
    const float* inX[2] = {x, y};

    dim3 b256(256);

    // 1. convert inputs
    convert_in<<<dim3(NROWS * DIM / 4 / 256, 2), b256>>>(x, y, Xh[0], Xl[0], Xh[1], Xl[1]);

    // 2. convert all 8 weight matrices (transposed planes)
    {
        WJobs wj;
        for (int i = 0; i < 8; i++) { wj.src[i] = W[i]; wj.h[i] = Wh[i]; wj.l[i] = Wl[i]; }
        convert_w<<<dim3(64, 64, 8), b256>>>(wj);
    }

    // 3. K,Q projections with fused transpose emission (z: Kq, Qq, Kf, Qf)
    {
        Jobs js = {};
        // weight idx: K=0/4, Q=1/5 per branch
        int widx[4] = {0, 1, 4, 5};
        u16* th[4] = {Kth[0], Qth[0], Kth[1], Qth[1]};
        u16* tl[4] = {Ktl[0], Qtl[0], Ktl[1], Qtl[1]};
        for (int z = 0; z < 4; z++) {
            int br = z >> 1;
            js.j[z].Ah = Xh[br]; js.j[z].Al = Xl[br];
            js.j[z].Bh = Wh[widx[z]]; js.j[z].Bl = Wl[widx[z]];
            js.j[z].bias = B[widx[z]];
            js.j[z].Eh = th[z]; js.j[z].El = tl[z];
        }
        gemm_fp16x3<2, true, false><<<dim3(16, 64, 4), b256, SMEM_TOTAL>>>(js, NROWS, DIM, DIM);
    }

    // 4. V projections (z: branch)
    {
        Jobs js = {};
        for (int z = 0; z < 2; z++) {
            js.j[z].Ah = Xh[z]; js.j[z].Al = Xl[z];
            js.j[z].Bh = Wh[2 + 4 * z]; js.j[z].Bl = Wl[2 + 4 * z];
            js.j[z].bias = B[2 + 4 * z];
            js.j[z].Eh = Vh[z]; js.j[z].El = Vl[z];
        }
        gemm_fp16x3<1, true, false><<<dim3(16, 64, 2), b256, SMEM_TOTAL>>>(js, NROWS, DIM, DIM);
    }

    // 5. att = Q^T K  (M=N=2048, K=8192) -> fp32 logits straight into d_out
    {
        Jobs js = {};
        for (int z = 0; z < 2; z++) {
            js.j[z].Ah = Qth[z]; js.j[z].Al = Qtl[z];
            js.j[z].Bh = Kth[z]; js.j[z].Bl = Ktl[z];
            js.j[z].C = att[z];
        }
        gemm_fp16x3<0, false, false><<<dim3(16, 16, 2), b256, SMEM_TOTAL>>>(js, DIM, DIM, NROWS);
    }

    // 6. softmax in place + emit w planes
    softmax_kernel<<<dim3(DIM, 2), b256>>>(att[0], att[1], wh[0], wl[0], wh[1], wl[1]);

    // 7. out = V @ w^T
    {
        Jobs js = {};
        for (int z = 0; z < 2; z++) {
            js.j[z].Ah = Vh[z]; js.j[z].Al = Vl[z];
            js.j[z].Bh = wh[z]; js.j[z].Bl = wl[z];
            js.j[z].Eh = Oh[z]; js.j[z].El = Ol[z];
        }
        gemm_fp16x3<1, false, false><<<dim3(16, 64, 2), b256, SMEM_TOTAL>>>(js, NROWS, DIM, DIM);
    }

    // 8. y = out @ Ow + Ob + X
    {
        Jobs js = {};
        for (int z = 0; z < 2; z++) {
            js.j[z].Ah = Oh[z]; js.j[z].Al = Ol[z];
            js.j[z].Bh = Wh[3 + 4 * z]; js.j[z].Bl = Wl[3 + 4 * z];
            js.j[z].bias = B[3 + 4 * z];
            js.j[z].res = inX[z];
            js.j[z].C = outY[z];
        }
        gemm_fp16x3<0, true, true><<<dim3(16, 64, 2), b256, SMEM_TOTAL>>>(js, NROWS, DIM, DIM);
    }
}

// round 6
// speedup vs baseline: 1.0705x; 1.0705x over previous
#include <cuda_runtime.h>
#include <cuda_fp16.h>
#include <float.h>

#define NROWS 8192
#define DIM   2048

typedef unsigned short u16;
typedef unsigned int   u32;
typedef unsigned long long u64;

// ---------------- scratch (device globals; no allocation allowed) ----------------
__device__ u16 g_Xh[2][(size_t)NROWS*DIM], g_Xl[2][(size_t)NROWS*DIM];
__device__ u16 g_Wh[8][(size_t)DIM*DIM],   g_Wl[8][(size_t)DIM*DIM];
__device__ u16 g_Kth[2][(size_t)NROWS*DIM], g_Ktl[2][(size_t)NROWS*DIM];
__device__ u16 g_Qth[2][(size_t)NROWS*DIM], g_Qtl[2][(size_t)NROWS*DIM];
__device__ u16 g_Vh[2][(size_t)NROWS*DIM],  g_Vl[2][(size_t)NROWS*DIM];
__device__ u16 g_wh[2][(size_t)DIM*DIM],    g_wl[2][(size_t)DIM*DIM];
__device__ u16 g_Oh[2][(size_t)NROWS*DIM],  g_Ol[2][(size_t)NROWS*DIM];

// ---------------- helpers ----------------
__device__ __forceinline__ u32 smem_u32(const void* p) {
    u32 a;
    asm("{ .reg .u64 t; cvta.to.shared.u64 t, %1; cvt.u32.u64 %0, t; }" : "=r"(a) : "l"(p));
    return a;
}

constexpr float INV2048 = 1.0f / 2048.0f;

// split fp32 -> fp16 hi + fp16 lo*2048 (scaled so correction products stay normal-range)
__device__ __forceinline__ void split1h(float v, u16& h, u16& l) {
    __half hh = __float2half_rn(v);
    float r = (v - __half2float(hh)) * 2048.0f;
    __half ll = __float2half_rn(r);
    h = __half_as_ushort(hh);
    l = __half_as_ushort(ll);
}

__device__ __forceinline__ float2 corr2f(u32 c) {
    __half2 h = *(__half2*)&c;
    return __half22float2(h);
}

#define CP_ASYNC16(dst, src) \
    asm volatile("cp.async.cg.shared.global [%0], [%1], 16;" :: "r"(dst), "l"(src))
#define CP_COMMIT()  asm volatile("cp.async.commit_group;" ::: "memory")
#define CP_WAIT0()   asm volatile("cp.async.wait_group 0;" ::: "memory")
#define CP_WAIT1()   asm volatile("cp.async.wait_group 1;" ::: "memory")

#define LDSM_X4(r, addr) \
    asm volatile("ldmatrix.sync.aligned.m8n8.x4.shared.b16 {%0,%1,%2,%3}, [%4];" \
        : "=r"((r)[0]), "=r"((r)[1]), "=r"((r)[2]), "=r"((r)[3]) : "r"(addr))

#define MMA16816F(d, a, b) \
    asm volatile("mma.sync.aligned.m16n8k16.row.col.f32.f16.f16.f32 " \
        "{%0,%1,%2,%3}, {%4,%5,%6,%7}, {%8,%9}, {%0,%1,%2,%3};" \
        : "+f"((d)[0]), "+f"((d)[1]), "+f"((d)[2]), "+f"((d)[3]) \
        : "r"((a)[0]), "r"((a)[1]), "r"((a)[2]), "r"((a)[3]), "r"((b)[0]), "r"((b)[1]))

#define MMA16816H(d, a, b) \
    asm volatile("mma.sync.aligned.m16n8k16.row.col.f16.f16.f16.f16 " \
        "{%0,%1}, {%2,%3,%4,%5}, {%6,%7}, {%0,%1};" \
        : "+r"((d)[0]), "+r"((d)[1]) \
        : "r"((a)[0]), "r"((a)[1]), "r"((a)[2]), "r"((a)[3]), "r"((b)[0]), "r"((b)[1]))

// ---------------- batched GEMM jobs ----------------
struct Job {
    const u16 *Ah, *Al, *Bh, *Bl;
    const float *bias, *res;
    float *C;
    u16 *Eh, *El;
};
struct Jobs { Job j[4]; };

// ---------------- GEMM: C[M,N] = A * B^T via fp16x3 split ----------------
// CTA tile 128x64, 128 threads (4 warps, warp tile 64x32), 2 CTAs/SM.
// main pass f32 accum; two correction passes share one f16 accumulator (x2048 scaled lo)
// EMODE: 0 = fp32 C out, 1 = emit split planes [M][N], 2 = emit transposed planes [N][M]
constexpr int A_PLANE = 128 * 128;   // 16KB (128 rows x 64 fp16)
constexpr int B_PLANE = 64 * 128;    // 8KB  (64 rows x 64 fp16)
constexpr int STAGE_BYTES = 2 * A_PLANE + 2 * B_PLANE;  // 48KB: [Ah][Al][Bh][Bl]
constexpr int SMEM_TOTAL = 2 * STAGE_BYTES;             // 96KB, 2-stage

template <int EMODE, bool BIAS, bool RES>
__global__ void __launch_bounds__(128, 2) gemm_fp16x3(Jobs jobs, int M, int N, int K) {
    extern __shared__ char smem[];
    const Job j = jobs.j[blockIdx.z];
    const int tid = threadIdx.x;
    const int lane = tid & 31;
    const int wid = tid >> 5;
    const int warpM = wid & 1;   // 2 x 64 rows
    const int warpN = wid >> 1;  // 2 x 32 cols
    const int m0 = blockIdx.y * 128;
    const int n0 = blockIdx.x * 64;
    const u32 sb = smem_u32(smem);

    float acc[4][4][4];
    u32 corr[4][4][2];
#pragma unroll
    for (int a = 0; a < 4; a++)
#pragma unroll
        for (int b = 0; b < 4; b++) {
#pragma unroll
            for (int c = 0; c < 4; c++) acc[a][b][c] = 0.f;
            corr[a][b][0] = 0u; corr[a][b][1] = 0u;
        }

    auto issue = [&](int t) {
        const int k0 = t * 64;
        const u32 stg = sb + (t & 1) * STAGE_BYTES;
        // A planes: 128 rows x 8 chunks = 1024 vec16 -> 8 iters of 128 threads
#pragma unroll
        for (int p = 0; p < 2; p++) {
            const u16* src = p ? j.Al : j.Ah;
            const u32 pb = stg + p * A_PLANE;
#pragma unroll
            for (int it = 0; it < 8; it++) {
                int idx = tid + it * 128;
                int r = idx >> 3, c = idx & 7;
                CP_ASYNC16(pb + r * 128 + ((c ^ (r & 7)) << 4),
                           src + (size_t)(m0 + r) * K + k0 + c * 8);
            }
        }
        // B planes: 64 rows x 8 chunks = 512 vec16 -> 4 iters
#pragma unroll
        for (int p = 0; p < 2; p++) {
            const u16* src = p ? j.Bl : j.Bh;
            const u32 pb = stg + 2 * A_PLANE + p * B_PLANE;
#pragma unroll
            for (int it = 0; it < 4; it++) {
                int idx = tid + it * 128;
                int r = idx >> 3, c = idx & 7;
                CP_ASYNC16(pb + r * 128 + ((c ^ (r & 7)) << 4),
                           src + (size_t)(n0 + r) * K + k0 + c * 8);
            }
        }
    };

    issue(0); CP_COMMIT();

    const int T = K / 64;
    for (int t = 0; t < T; t++) {
        if (t + 1 < T) { issue(t + 1); CP_COMMIT(); CP_WAIT1(); }
        else           { CP_WAIT0(); }
        __syncthreads();  // data for tile t visible to all warps

        const u32 stg = sb + (t & 1) * STAGE_BYTES;
        const u32 aH = stg, aL = stg + A_PLANE;
        const u32 bH = stg + 2 * A_PLANE, bL = stg + 2 * A_PLANE + B_PLANE;

#pragma unroll
        for (int step = 0; step < 4; step++) {
            u32 ra[4][4], la[4][4];
#pragma unroll
            for (int mf = 0; mf < 4; mf++) {
                int row = warpM * 64 + mf * 16 + (lane & 15);
                int chunk = step * 2 + (lane >> 4);
                u32 off = row * 128 + ((chunk ^ (row & 7)) << 4);
                LDSM_X4(ra[mf], aH + off);
                LDSM_X4(la[mf], aL + off);
            }
            u32 rb[2][4], lb[2][4];
#pragma unroll
            for (int np = 0; np < 2; np++) {
                int jj = lane >> 3;
                int row = warpN * 32 + np * 16 + ((jj >> 1) << 3) + (lane & 7);
                int chunk = step * 2 + (jj & 1);
                u32 off = row * 128 + ((chunk ^ (row & 7)) << 4);
                LDSM_X4(rb[np], bH + off);
                LDSM_X4(lb[np], bL + off);
            }
            // main: f32 accum
#pragma unroll
            for (int mf = 0; mf < 4; mf++)
#pragma unroll
                for (int nf = 0; nf < 4; nf++)
                    MMA16816F(acc[mf][nf], ra[mf], &rb[nf >> 1][(nf & 1) * 2]);
            // corrections: shared f16 accum (values ~2048x true scale)
#pragma unroll
            for (int mf = 0; mf < 4; mf++)
#pragma unroll
                for (int nf = 0; nf < 4; nf++)
                    MMA16816H(corr[mf][nf], ra[mf], &lb[nf >> 1][(nf & 1) * 2]);
#pragma unroll
            for (int mf = 0; mf < 4; mf++)
#pragma unroll
                for (int nf = 0; nf < 4; nf++)
                    MMA16816H(corr[mf][nf], la[mf], &rb[nf >> 1][(nf & 1) * 2]);
        }
        __syncthreads();  // all warps done reading buf t&1 before it is refilled
    }

    if (EMODE == 2) {
        // transposed emission: stage fp32 through smem, then coalesced plane stores
        float* stg = (float*)smem;
#pragma unroll
        for (int mf = 0; mf < 4; mf++) {
#pragma unroll
            for (int nf = 0; nf < 4; nf++) {
                float2 c0 = corr2f(corr[mf][nf][0]);
                float2 c1 = corr2f(corr[mf][nf][1]);
                const float* a = acc[mf][nf];
                int cl = warpN * 32 + nf * 8 + (lane & 3) * 2;
                int rl0 = warpM * 64 + mf * 16 + (lane >> 2);
                stg[cl * 132 + rl0]           = a[0] + c0.x * INV2048;
                stg[(cl + 1) * 132 + rl0]     = a[1] + c0.y * INV2048;
                stg[cl * 132 + rl0 + 8]       = a[2] + c1.x * INV2048;
                stg[(cl + 1) * 132 + rl0 + 8] = a[3] + c1.y * INV2048;
            }
        }
        __syncthreads();
#pragma unroll 4
        for (int i = 0; i < 64; i++) {
            int idx = tid + i * 128;
            int c = idx >> 7, r = idx & 127;
            float v = stg[c * 132 + r];
            if (BIAS) v += j.bias[n0 + c];
            u16 h, l;
            split1h(v, h, l);
            size_t o = (size_t)(n0 + c) * M + m0 + r;
            j.Eh[o] = h;
            j.El[o] = l;
        }
        return;
    }

    // direct register epilogue (EMODE 0/1)
#pragma unroll
    for (int mf = 0; mf < 4; mf++) {
        const int rbase = m0 + warpM * 64 + mf * 16 + (lane >> 2);
#pragma unroll
        for (int nf = 0; nf < 4; nf++) {
            const int c = n0 + warpN * 32 + nf * 8 + (lane & 3) * 2;
            const float* a = acc[mf][nf];
            float2 cr[2] = {corr2f(corr[mf][nf][0]), corr2f(corr[mf][nf][1])};
#pragma unroll
            for (int h = 0; h < 2; h++) {
                const int r = rbase + h * 8;
                float vx = a[h * 2 + 0] + cr[h].x * INV2048;
                float vy = a[h * 2 + 1] + cr[h].y * INV2048;
                if (BIAS) {
                    float2 b2 = *(const float2*)&j.bias[c];
                    vx += b2.x; vy += b2.y;
                }
                if (RES) {
                    float2 r2 = *(const float2*)&j.res[(size_t)r * N + c];
                    vx += r2.x; vy += r2.y;
                }
                if (EMODE == 1) {
                    u16 hx, lx, hy, ly;
                    split1h(vx, hx, lx);
                    split1h(vy, hy, ly);
                    *(ushort2*)&j.Eh[(size_t)r * N + c] = make_ushort2(hx, hy);
                    *(ushort2*)&j.El[(size_t)r * N + c] = make_ushort2(lx, ly);
                } else {
                    *(float2*)&j.C[(size_t)r * N + c] = make_float2(vx, vy);
                }
            }
        }
    }
}

// ---------------- conversion kernels ----------------
__global__ void __launch_bounds__(256) convert_in(const float* __restrict__ x,
                                                  const float* __restrict__ y,
                                                  u16* __restrict__ xh, u16* __restrict__ xl,
                                                  u16* __restrict__ yh, u16* __restrict__ yl) {
    const float* in = blockIdx.y ? y : x;
    u16* hi = blockIdx.y ? yh : xh;
    u16* lo = blockIdx.y ? yl : xl;
    size_t i = (size_t)blockIdx.x * 256 + threadIdx.x;
    float4 v = ((const float4*)in)[i];
    ushort4 h, l;
    split1h(v.x, h.x, l.x); split1h(v.y, h.y, l.y);
    split1h(v.z, h.z, l.z); split1h(v.w, h.w, l.w);
    ((ushort4*)hi)[i] = h;
    ((ushort4*)lo)[i] = l;
}

struct WJobs {
    const float* src[8];
    u16* h[8];
    u16* l[8];
};

// each W [in][out] fp32 -> planes [out][in] fp16 hi/lo (scaled lo)
__global__ void __launch_bounds__(256) convert_w(WJobs w) {
    __shared__ float t[32][33];
    const float* in = w.src[blockIdx.z];
    u16* hi = w.h[blockIdx.z];
    u16* lo = w.l[blockIdx.z];
    const int c0 = blockIdx.x * 32, r0 = blockIdx.y * 32;
    const int tx = threadIdx.x & 31, ty = threadIdx.x >> 5;
#pragma unroll
    for (int jj = 0; jj < 32; jj += 8)
        t[ty + jj][tx] = in[(size_t)(r0 + ty + jj) * DIM + c0 + tx];
    __syncthreads();
#pragma unroll
    for (int jj = 0; jj < 32; jj += 8) {
        float v = t[tx][ty + jj];
        u16 h, l;
        split1h(v, h, l);
        size_t o = (size_t)(c0 + ty + jj) * DIM + r0 + tx;
        hi[o] = h;
        lo[o] = l;
    }
}

// ---------------- softmax (in-place on d_out att region + emit fp16 planes) ----------------
__global__ void __launch_bounds__(256) softmax_kernel(float* att0, float* att1,
                                                      u16* wh0, u16* wl0,
                                                      u16* wh1, u16* wl1) {
    float* att = blockIdx.y ? att1 : att0;
    u16* wh = blockIdx.y ? wh1 : wh0;
    u16* wl = blockIdx.y ? wl1 : wl0;
    const int row = blockIdx.x;
    const int tid = threadIdx.x;
    float* r = att + (size_t)row * DIM;
    __shared__ float red[8];

    float v[8];
    float mx = -FLT_MAX;
#pragma unroll
    for (int i = 0; i < 8; i++) {
        v[i] = r[tid + i * 256];
        mx = fmaxf(mx, v[i]);
    }
#pragma unroll
    for (int o = 16; o > 0; o >>= 1) mx = fmaxf(mx, __shfl_xor_sync(0xffffffffu, mx, o));
    if ((tid & 31) == 0) red[tid >> 5] = mx;
    __syncthreads();
    mx = red[0];
#pragma unroll
    for (int w = 1; w < 8; w++) mx = fmaxf(mx, red[w]);
    __syncthreads();

    float s = 0.f;
#pragma unroll
    for (int i = 0; i < 8; i++) {
        v[i] = __expf(v[i] - mx);
        s += v[i];
    }
#pragma unroll
    for (int o = 16; o > 0; o >>= 1) s += __shfl_xor_sync(0xffffffffu, s, o);
    if ((tid & 31) == 0) red[tid >> 5] = s;
    __syncthreads();
    s = red[0];
#pragma unroll
    for (int w = 1; w < 8; w++) s += red[w];
    const float inv = 1.f / s;

#pragma unroll
    for (int i = 0; i < 8; i++) {
        float w = v[i] * inv;
        int col = tid + i * 256;
        r[col] = w;
        u16 h, l;
        split1h(w, h, l);
        wh[(size_t)row * DIM + col] = h;
        wl[(size_t)row * DIM + col] = l;
    }
}

// ---------------- host driver ----------------
extern "C" void kernel_launch(void* const* d_in, const int* in_sizes, int n_in,
                              void* d_out, int out_size) {
    cudaFuncSetAttribute(gemm_fp16x3<2, true, false>, cudaFuncAttributeMaxDynamicSharedMemorySize, SMEM_TOTAL);
    cudaFuncSetAttribute(gemm_fp16x3<1, true, false>, cudaFuncAttributeMaxDynamicSharedMemorySize, SMEM_TOTAL);
    cudaFuncSetAttribute(gemm_fp16x3<0, false, false>, cudaFuncAttributeMaxDynamicSharedMemorySize, SMEM_TOTAL);
    cudaFuncSetAttribute(gemm_fp16x3<1, false, false>, cudaFuncAttributeMaxDynamicSharedMemorySize, SMEM_TOTAL);
    cudaFuncSetAttribute(gemm_fp16x3<0, true, true>, cudaFuncAttributeMaxDynamicSharedMemorySize, SMEM_TOTAL);

    const float* x = (const float*)d_in[0];
    const float* y = (const float*)d_in[1];
    const float* W[8];
    const float* B[8];
    for (int i = 0; i < 8; i++) {
        W[i] = (const float*)d_in[2 + 2 * i];
        B[i] = (const float*)d_in[3 + 2 * i];
    }

    u16 *Xh[2], *Xl[2], *Wh[8], *Wl[8], *Kth[2], *Ktl[2], *Qth[2], *Qtl[2];
    u16 *Vh[2], *Vl[2], *wh[2], *wl[2], *Oh[2], *Ol[2];
    u16 *base;
    cudaGetSymbolAddress((void**)&base, g_Xh);
    for (int b = 0; b < 2; b++) { Xh[b] = base + (size_t)b * NROWS * DIM; }
    cudaGetSymbolAddress((void**)&base, g_Xl);
    for (int b = 0; b < 2; b++) { Xl[b] = base + (size_t)b * NROWS * DIM; }
    cudaGetSymbolAddress((void**)&base, g_Wh);
    for (int i = 0; i < 8; i++) { Wh[i] = base + (size_t)i * DIM * DIM; }
    cudaGetSymbolAddress((void**)&base, g_Wl);
    for (int i = 0; i < 8; i++) { Wl[i] = base + (size_t)i * DIM * DIM; }
    cudaGetSymbolAddress((void**)&base, g_Kth);
    for (int b = 0; b < 2; b++) { Kth[b] = base + (size_t)b * NROWS * DIM; }
    cudaGetSymbolAddress((void**)&base, g_Ktl);
    for (int b = 0; b < 2; b++) { Ktl[b] = base + (size_t)b * NROWS * DIM; }
    cudaGetSymbolAddress((void**)&base, g_Qth);
    for (int b = 0; b < 2; b++) { Qth[b] = base + (size_t)b * NROWS * DIM; }
    cudaGetSymbolAddress((void**)&base, g_Qtl);
    for (int b = 0; b < 2; b++) { Qtl[b] = base + (size_t)b * NROWS * DIM; }
    cudaGetSymbolAddress((void**)&base, g_Vh);
    for (int b = 0; b < 2; b++) { Vh[b] = base + (size_t)b * NROWS * DIM; }
    cudaGetSymbolAddress((void**)&base, g_Vl);
    for (int b = 0; b < 2; b++) { Vl[b] = base + (size_t)b * NROWS * DIM; }
    cudaGetSymbolAddress((void**)&base, g_wh);
    for (int b = 0; b < 2; b++) { wh[b] = base + (size_t)b * DIM * DIM; }
    cudaGetSymbolAddress((void**)&base, g_wl);
    for (int b = 0; b < 2; b++) { wl[b] = base + (size_t)b * DIM * DIM; }
    cudaGetSymbolAddress((void**)&base, g_Oh);
    for (int b = 0; b < 2; b++) { Oh[b] = base + (size_t)b * NROWS * DIM; }
    cudaGetSymbolAddress((void**)&base, g_Ol);
    for (int b = 0; b < 2; b++) { Ol[b] = base + (size_t)b * NROWS * DIM; }

    float* out = (float*)d_out;
    float* outQy   = out;
    float* outQatt = outQy + (size_t)NROWS * DIM;
    float* outFy   = outQatt + (size_t)DIM * DIM;
    float* outFatt = outFy + (size_t)NROWS * DIM;
    float* att[2] = {outQatt, outFatt};
    float* outY[2] = {outQy, outFy};
    const float* inX[2] = {x, y};

    dim3 b256(256);
    dim3 b128(128);

    // 1. convert inputs
    convert_in<<<dim3(NROWS * DIM / 4 / 256, 2), b256>>>(x, y, Xh[0], Xl[0], Xh[1], Xl[1]);

    // 2. convert all 8 weight matrices (transposed planes)
    {
        WJobs wj;
        for (int i = 0; i < 8; i++) { wj.src[i] = W[i]; wj.h[i] = Wh[i]; wj.l[i] = Wl[i]; }
        convert_w<<<dim3(64, 64, 8), b256>>>(wj);
    }

    // 3. K,Q projections with fused transpose emission (z: Kq, Qq, Kf, Qf)
    {
        Jobs js = {};
        int widx[4] = {0, 1, 4, 5};
        u16* th[4] = {Kth[0], Qth[0], Kth[1], Qth[1]};
        u16* tl[4] = {Ktl[0], Qtl[0], Ktl[1], Qtl[1]};
        for (int z = 0; z < 4; z++) {
            int br = z >> 1;
            js.j[z].Ah = Xh[br]; js.j[z].Al = Xl[br];
            js.j[z].Bh = Wh[widx[z]]; js.j[z].Bl = Wl[widx[z]];
            js.j[z].bias = B[widx[z]];
            js.j[z].Eh = th[z]; js.j[z].El = tl[z];
        }
        gemm_fp16x3<2, true, false><<<dim3(32, 64, 4), b128, SMEM_TOTAL>>>(js, NROWS, DIM, DIM);
    }

    // 4. V projections (z: branch)
    {
        Jobs js = {};
        for (int z = 0; z < 2; z++) {
            js.j[z].Ah = Xh[z]; js.j[z].Al = Xl[z];
            js.j[z].Bh = Wh[2 + 4 * z]; js.j[z].Bl = Wl[2 + 4 * z];
            js.j[z].bias = B[2 + 4 * z];
            js.j[z].Eh = Vh[z]; js.j[z].El = Vl[z];
        }
        gemm_fp16x3<1, true, false><<<dim3(32, 64, 2), b128, SMEM_TOTAL>>>(js, NROWS, DIM, DIM);
    }

    // 5. att = Q^T K  (M=N=2048, K=8192) -> fp32 logits straight into d_out
    {
        Jobs js = {};
        for (int z = 0; z < 2; z++) {
            js.j[z].Ah = Qth[z]; js.j[z].Al = Qtl[z];
            js.j[z].Bh = Kth[z]; js.j[z].Bl = Ktl[z];
            js.j[z].C = att[z];
        }
        gemm_fp16x3<0, false, false><<<dim3(32, 16, 2), b128, SMEM_TOTAL>>>(js, DIM, DIM, NROWS);
    }

    // 6. softmax in place + emit w planes
    softmax_kernel<<<dim3(DIM, 2), b256>>>(att[0], att[1], wh[0], wl[0], wh[1], wl[1]);

    // 7. out = V @ w^T
    {
        Jobs js = {};
        for (int z = 0; z < 2; z++) {
            js.j[z].Ah = Vh[z]; js.j[z].Al = Vl[z];
            js.j[z].Bh = wh[z]; js.j[z].Bl = wl[z];
            js.j[z].Eh = Oh[z]; js.j[z].El = Ol[z];
        }
        gemm_fp16x3<1, false, false><<<dim3(32, 64, 2), b128, SMEM_TOTAL>>>(js, NROWS, DIM, DIM);
    }

    // 8. y = out @ Ow + Ob + X
    {
        Jobs js = {};
        for (int z = 0; z < 2; z++) {
            js.j[z].Ah = Oh[z]; js.j[z].Al = Ol[z];
            js.j[z].Bh = Wh[3 + 4 * z]; js.j[z].Bl = Wl[3 + 4 * z];
            js.j[z].bias = B[3 + 4 * z];
            js.j[z].res = inX[z];
            js.j[z].C = outY[z];
        }
        gemm_fp16x3<0, true, true><<<dim3(32, 64, 2), b128, SMEM_TOTAL>>>(js, NROWS, DIM, DIM);
    }
}